// round 7
// baseline (speedup 1.0000x reference)
#include <cuda_runtime.h>
#include <cuda_fp16.h>
#include <cstdint>

#define Bsz 8
#define Pp  16
#define Dd  512
#define Ee  8192
#define Mm  8192
#define LOG2E 1.4426950408889634f

// Scratch (device globals)
__device__ __half g_Hh[(size_t)Mm * Dd];    // fp16(H), row-major [M][512]
__device__ __half g_W2h[(size_t)Ee * Dd];   // fp16 of (W2*log2e)^T, [E][512]
__device__ __half g_E[(size_t)Mm * Ee];     // 128 MB exp(relu(logits)) in fp16
__device__ float g_Zpart[64 * Ee];
__device__ float g_Zinv[Bsz * Ee];

// ======================= PTX helpers =======================
__device__ __forceinline__ uint32_t smem_u32(const void* p) {
    uint32_t a;
    asm("{ .reg .u64 t; cvta.to.shared.u64 t, %1; cvt.u32.u64 %0, t; }" : "=r"(a) : "l"(p));
    return a;
}
#define CP16(dst, src) \
    asm volatile("cp.async.cg.shared.global [%0], [%1], 16;" :: "r"(dst), "l"(src) : "memory")
#define CP_COMMIT() asm volatile("cp.async.commit_group;" ::: "memory")
#define CP_WAIT(n)  asm volatile("cp.async.wait_group %0;" :: "n"(n) : "memory")

__device__ __forceinline__ void ldsm4(uint32_t* r, uint32_t addr) {
    asm volatile("ldmatrix.sync.aligned.m8n8.x4.shared.b16 {%0,%1,%2,%3}, [%4];"
                 : "=r"(r[0]), "=r"(r[1]), "=r"(r[2]), "=r"(r[3]) : "r"(addr));
}
// f16-accumulator MMA, fresh start (C = zero regs, D written)
__device__ __forceinline__ void mma_f16_zero(uint32_t* d, const uint32_t* a, const uint32_t* b) {
    asm volatile("mma.sync.aligned.m16n8k16.row.col.f16.f16.f16.f16 "
                 "{%0,%1}, {%2,%3,%4,%5}, {%6,%7}, {%8,%9};"
                 : "=r"(d[0]), "=r"(d[1])
                 : "r"(a[0]), "r"(a[1]), "r"(a[2]), "r"(a[3]),
                   "r"(b[0]), "r"(b[1]), "r"(0u), "r"(0u));
}
// f16-accumulator MMA, accumulate in place
__device__ __forceinline__ void mma_f16_acc(uint32_t* d, const uint32_t* a, const uint32_t* b) {
    asm volatile("mma.sync.aligned.m16n8k16.row.col.f16.f16.f16.f16 "
                 "{%0,%1}, {%2,%3,%4,%5}, {%6,%7}, {%0,%1};"
                 : "+r"(d[0]), "+r"(d[1])
                 : "r"(a[0]), "r"(a[1]), "r"(a[2]), "r"(a[3]), "r"(b[0]), "r"(b[1]));
}
__device__ __forceinline__ float ex2f(float x) {
    float r;
    asm("ex2.approx.ftz.f32 %0, %1;" : "=f"(r) : "f"(x));
    return r;
}

// ======================= K1: hidden layer -> fp16 =======================
__global__ void k_hidden(const float* __restrict__ x,
                         const float* __restrict__ W1,
                         const float* __restrict__ b1) {
    int row = blockIdx.x;
    __shared__ float xs[Pp];
    int tid = threadIdx.x;                  // = d (512 threads)
    if (tid < Pp) xs[tid] = x[row * Pp + tid];
    __syncthreads();
    float acc = b1[tid];
#pragma unroll
    for (int p = 0; p < Pp; p++) acc = fmaf(xs[p], W1[p * Dd + tid], acc);
    g_Hh[(size_t)row * Dd + tid] = __float2half(fmaxf(acc, 0.0f));
}

// ======================= K1b: W2 * log2e, transpose -> fp16 =======================
__global__ void k_w2conv(const float* __restrict__ W2) {
    __shared__ float ts[64][65];
    int e0 = blockIdx.x * 64, k0 = blockIdx.y * 64;
    int tid = threadIdx.x;
#pragma unroll
    for (int idx = tid; idx < 4096; idx += 256) {
        int i = idx >> 6, j = idx & 63;     // i=k, j=e
        ts[i][j] = W2[(size_t)(k0 + i) * Ee + e0 + j] * LOG2E;
    }
    __syncthreads();
#pragma unroll
    for (int idx = tid; idx < 4096; idx += 256) {
        int j = idx >> 6, i = idx & 63;     // j=e, i=k
        g_W2h[(size_t)(e0 + j) * Dd + k0 + i] = __float2half(ts[i][j]);
    }
}

// ======================= K2: fp16-acc mma GEMM + fused epilogue =======================
// CTA 128x128, 512 threads (warp grid 2m x 8n, warp tile 64x16).
// BK=64 per stage, 8 stages, 3-stage cp.async ring.
// fp16 accumulation per stage (K=64 chunk), spilled to fp32 masters.
#define LDT      72                         // padded row in fp16 elems (144 B)
#define TILE_B   (128 * 144)                // 18432
#define STAGE_B  (2 * TILE_B)               // 36864
#define NSTG     3
#define SMEM_DYN (NSTG * STAGE_B)           // 110592

__global__ __launch_bounds__(512, 1) void k_gemm_mma(const float* __restrict__ b2) {
    extern __shared__ char sm[];
    uint32_t smb = smem_u32(sm);
    int tid = threadIdx.x;
    int wid = tid >> 5, lane = tid & 31;
    int wm = wid >> 3, wn = wid & 7;            // 2(m) x 8(n); warp tile 64x16

    // L2-friendly swizzle: strips of (64 row-tiles x 8 col-tiles)
    int bid = blockIdx.x;
    int rt = (bid & 511) >> 3;
    int ct = ((bid >> 9) << 3) | (bid & 7);
    int row0 = rt * 128, col0 = ct * 128;

    float c[4][2][4];                           // fp32 masters: 4 m-tiles x 2 n-tiles
#pragma unroll
    for (int i = 0; i < 4; i++)
#pragma unroll
        for (int j = 0; j < 2; j++)
#pragma unroll
            for (int q = 0; q < 4; q++) c[i][j][q] = 0.f;

    // stage loader: 4 cp16 per thread (A 2, B 2)
    auto load_stage = [&](int s, int st) {
        uint32_t sb = smb + st * STAGE_B;
#pragma unroll
        for (int v = 0; v < 2; v++) {
            int idx = tid + v * 512;            // 0..1023
            int r = idx >> 3, cq = idx & 7;     // 8 x 16B per 128B row
            uint32_t soff = r * 144 + cq * 16;
            size_t ga = ((size_t)(row0 + r) << 10) + (size_t)s * 128 + cq * 16;
            size_t gb = ((size_t)(col0 + r) << 10) + (size_t)s * 128 + cq * 16;
            CP16(sb + soff,          (const char*)g_Hh  + ga);
            CP16(sb + TILE_B + soff, (const char*)g_W2h + gb);
        }
    };

    load_stage(0, 0); CP_COMMIT();
    load_stage(1, 1); CP_COMMIT();

    for (int s = 0; s < 8; s++) {
        if (s + 2 < 8) { load_stage(s + 2, (s + 2) % NSTG); CP_COMMIT(); }
        if (s < 6)      CP_WAIT(2);
        else if (s < 7) CP_WAIT(1);
        else            CP_WAIT(0);
        __syncthreads();

        uint32_t base = smb + (s % NSTG) * STAGE_B;
        uint32_t c16[4][2][2];                  // fp16 chunk accumulators
#pragma unroll
        for (int ks = 0; ks < 4; ks++) {
            uint32_t a[4][4], bf[4];
            {
                int arow = wm * 64 + (lane & 15);
                int ak = ks * 16 + ((lane >> 4) << 3);
                uint32_t aoff = base + (uint32_t)(arow * 144 + ak * 2);
#pragma unroll
                for (int i = 0; i < 4; i++) ldsm4(a[i], aoff + i * 16 * 144);
            }
            {
                int g = lane >> 3, r = lane & 7;
                int bn = wn * 16 + ((g >> 1) << 3) + r;
                int bk = ks * 16 + ((g & 1) << 3);
                ldsm4(bf, base + TILE_B + (uint32_t)(bn * 144 + bk * 2));
            }
#pragma unroll
            for (int i = 0; i < 4; i++)
#pragma unroll
                for (int j = 0; j < 2; j++) {
                    if (ks == 0) mma_f16_zero(c16[i][j], a[i], &bf[j * 2]);
                    else         mma_f16_acc (c16[i][j], a[i], &bf[j * 2]);
                }
        }
        // spill chunk (K=64) into fp32 masters
#pragma unroll
        for (int i = 0; i < 4; i++)
#pragma unroll
            for (int j = 0; j < 2; j++) {
                float2 lo = __half22float2(*reinterpret_cast<__half2*>(&c16[i][j][0]));
                float2 hi = __half22float2(*reinterpret_cast<__half2*>(&c16[i][j][1]));
                c[i][j][0] += lo.x; c[i][j][1] += lo.y;
                c[i][j][2] += hi.x; c[i][j][3] += hi.y;
            }
    }
    __syncthreads();   // protect smem reuse by epilogue

    // ---- epilogue: stage in smem (stride 130), bias + relu + ex2, fp16 writes ----
    float* eb = (float*)sm;                      // 128 x 130 floats = 66560 B
    float* red = (float*)(sm + 66560);           // 4 x 128 floats
#pragma unroll
    for (int i = 0; i < 4; i++) {
#pragma unroll
        for (int j = 0; j < 2; j++) {
            int r = wm * 64 + i * 16 + (lane >> 2);
            int cc = wn * 16 + j * 8 + (lane & 3) * 2;
            *(float2*)&eb[r * 130 + cc]       = make_float2(c[i][j][0], c[i][j][1]);
            *(float2*)&eb[(r + 8) * 130 + cc] = make_float2(c[i][j][2], c[i][j][3]);
        }
    }
    __syncthreads();
    {
        int col = tid & 127, q = tid >> 7;       // 4 quarters x 32 rows
        float bias = b2[col0 + col] * LOG2E;
        float csum = 0.f;
        size_t gbase = (size_t)(row0 + q * 32) * Ee + col0 + col;
#pragma unroll 8
        for (int r = 0; r < 32; r++) {
            float v = ex2f(fmaxf(eb[(q * 32 + r) * 130 + col] + bias, 0.0f));
            csum += v;
            g_E[gbase + (size_t)r * Ee] = __float2half(v);
        }
        red[q * 128 + col] = csum;
    }
    __syncthreads();
    if (tid < 128)
        g_Zpart[(size_t)rt * Ee + col0 + tid] =
            red[tid] + red[128 + tid] + red[256 + tid] + red[384 + tid];
}

// ======================= K2b: softmax denominators =======================
__global__ void k_zreduce() {
    int idx = blockIdx.x * blockDim.x + threadIdx.x;
    int b = idx >> 13;
    int e = idx & (Ee - 1);
    float s = 0.f;
#pragma unroll
    for (int i = 0; i < 8; i++) s += g_Zpart[(size_t)(b * 8 + i) * Ee + e];
    g_Zinv[idx] = 1.0f / s;
}

// ======================= K3: normalize * xp, transpose, avgpool (4 rows/CTA) =======================
#define RPC 4
__global__ void k_final(const float* __restrict__ x, float* __restrict__ out) {
    int b = blockIdx.x >> 8;                 // 256 CTAs per batch
    int row0 = blockIdx.x * RPC;
    __shared__ float zs[Ee];                 // 32 KB: Zinv for this batch
    __shared__ float t[Pp * 514];            // 32.9 KB
    __shared__ float xs[Pp];
    int tid = threadIdx.x;                   // 512 threads

    {   // load Zinv[b,:] once
        const float4* Z4 = (const float4*)(g_Zinv + (size_t)b * Ee);
        float4* zs4 = (float4*)zs;
#pragma unroll
        for (int i = 0; i < 4; i++) zs4[i * 512 + tid] = Z4[i * 512 + tid];
    }

    for (int r = 0; r < RPC; r++) {
        int row = row0 + r;
        __syncthreads();
        if (tid < Pp) xs[tid] = x[row * Pp + tid] * (1.0f / 3.0f);
        const __half2* E2 = (const __half2*)(g_E + (size_t)row * Ee);
#pragma unroll
        for (int i = 0; i < 8; i++) {
            int idx2 = i * 512 + tid;        // half2 index: e = 2*idx2
            __half2 e2 = E2[idx2];
            int d = idx2 >> 3;
            int p0 = (idx2 & 7) * 2;
            int e = idx2 * 2;
            t[p0 * 514 + d]       = __low2float(e2)  * zs[e];
            t[(p0 + 1) * 514 + d] = __high2float(e2) * zs[e + 1];
        }
        __syncthreads();
        int d = tid;
        size_t obase = ((size_t)row * Pp) * Dd + d;
#pragma unroll
        for (int p = 0; p < Pp; p++) {
            const float* tp = t + p * 514;
            float cc = tp[d];
            float l = (d > 0)   ? tp[d - 1] : 0.f;
            float rr = (d < 511) ? tp[d + 1] : 0.f;
            out[obase + (size_t)p * Dd] = xs[p] * (l + cc + rr);
        }
    }
}

// ======================= launch =======================
extern "C" void kernel_launch(void* const* d_in, const int* in_sizes, int n_in,
                              void* d_out, int out_size) {
    const float* x  = (const float*)d_in[0];
    const float* W1 = (const float*)d_in[1];
    const float* b1 = (const float*)d_in[2];
    const float* W2 = (const float*)d_in[3];
    const float* b2 = (const float*)d_in[4];
    float* out = (float*)d_out;

    static int smem_set = 0;
    if (!smem_set) {
        cudaFuncSetAttribute(k_gemm_mma, cudaFuncAttributeMaxDynamicSharedMemorySize, SMEM_DYN);
        smem_set = 1;
    }

    k_hidden<<<Mm, Dd>>>(x, W1, b1);
    k_w2conv<<<dim3(Ee / 64, Dd / 64), 256>>>(W2);
    k_gemm_mma<<<4096, 512, SMEM_DYN>>>(b2);
    k_zreduce<<<(Bsz * Ee) / 256, 256>>>();
    k_final<<<Mm / RPC, 512>>>(x, out);
}

// round 8
// speedup vs baseline: 1.2544x; 1.2544x over previous
#include <cuda_runtime.h>
#include <cuda_fp16.h>
#include <cstdint>

#define Bsz 8
#define Pp  16
#define Dd  512
#define Ee  8192
#define Mm  8192
#define LOG2E 1.4426950408889634f

// Scratch (device globals)
__device__ __half g_Hh[(size_t)Mm * Dd];    // fp16(H), row-major [M][512]
__device__ __half g_W2h[(size_t)Ee * Dd];   // fp16 of (W2*log2e)^T, [E][512]
__device__ __half g_E[(size_t)Mm * Ee];     // 128 MB exp(relu(logits)) in fp16
__device__ float g_Zpart[64 * Ee];
__device__ float g_Zinv[Bsz * Ee];

// ======================= PTX helpers =======================
__device__ __forceinline__ uint32_t smem_u32(const void* p) {
    uint32_t a;
    asm("{ .reg .u64 t; cvta.to.shared.u64 t, %1; cvt.u32.u64 %0, t; }" : "=r"(a) : "l"(p));
    return a;
}
#define CP16(dst, src) \
    asm volatile("cp.async.cg.shared.global [%0], [%1], 16;" :: "r"(dst), "l"(src) : "memory")
#define CP_COMMIT() asm volatile("cp.async.commit_group;" ::: "memory")
#define CP_WAIT(n)  asm volatile("cp.async.wait_group %0;" :: "n"(n) : "memory")

__device__ __forceinline__ void ldsm4(uint32_t* r, uint32_t addr) {
    asm volatile("ldmatrix.sync.aligned.m8n8.x4.shared.b16 {%0,%1,%2,%3}, [%4];"
                 : "=r"(r[0]), "=r"(r[1]), "=r"(r[2]), "=r"(r[3]) : "r"(addr));
}
__device__ __forceinline__ void mma16816(float* c, const uint32_t* a, const uint32_t* b) {
    asm volatile("mma.sync.aligned.m16n8k16.row.col.f32.f16.f16.f32 "
                 "{%0,%1,%2,%3}, {%4,%5,%6,%7}, {%8,%9}, {%0,%1,%2,%3};"
                 : "+f"(c[0]), "+f"(c[1]), "+f"(c[2]), "+f"(c[3])
                 : "r"(a[0]), "r"(a[1]), "r"(a[2]), "r"(a[3]), "r"(b[0]), "r"(b[1]));
}
__device__ __forceinline__ float ex2f(float x) {
    float r;
    asm("ex2.approx.ftz.f32 %0, %1;" : "=f"(r) : "f"(x));
    return r;
}

// ======================= K0: fused prep (hidden layer | W2 convert) =======================
// Blocks 0..511: hidden rows [bid*16, bid*16+16), W1 cached in smem.
// Blocks 512..1535: W2 * log2e transpose+fp16, 64x64 tiles.
__global__ __launch_bounds__(512) void k_prep(const float* __restrict__ x,
                                              const float* __restrict__ W1,
                                              const float* __restrict__ b1,
                                              const float* __restrict__ W2) {
    __shared__ float sbuf[8448];            // hidden: W1(8192)+xs(256); w2conv: ts 64x65
    int tid = threadIdx.x;
    if (blockIdx.x < 512) {
        int row0 = blockIdx.x * 16;
        float* W1s = sbuf;                  // [p][d] = p*512+d
        float* xs  = sbuf + 8192;           // [16][16]
        const float4* W14 = (const float4*)W1;
        float4* W1s4 = (float4*)W1s;
#pragma unroll
        for (int i = 0; i < 4; i++) W1s4[i * 512 + tid] = W14[i * 512 + tid];
        if (tid < 256) xs[tid] = x[row0 * Pp + tid];
        __syncthreads();
        float bb = b1[tid];
#pragma unroll
        for (int r = 0; r < 16; r++) {
            float acc = bb;
#pragma unroll
            for (int p = 0; p < Pp; p++) acc = fmaf(xs[r * Pp + p], W1s[p * Dd + tid], acc);
            g_Hh[(size_t)(row0 + r) * Dd + tid] = __float2half(fmaxf(acc, 0.0f));
        }
    } else {
        int bid = blockIdx.x - 512;         // 0..1023
        int e0 = (bid & 127) * 64, k0 = (bid >> 7) * 64;
        float (*ts)[65] = (float(*)[65])sbuf;
#pragma unroll
        for (int idx = tid; idx < 4096; idx += 512) {
            int i = idx >> 6, j = idx & 63; // i=k, j=e
            ts[i][j] = W2[(size_t)(k0 + i) * Ee + e0 + j] * LOG2E;
        }
        __syncthreads();
#pragma unroll
        for (int idx = tid; idx < 4096; idx += 512) {
            int j = idx >> 6, i = idx & 63; // j=e, i=k
            g_W2h[(size_t)(e0 + j) * Dd + k0 + i] = __float2half(ts[i][j]);
        }
    }
}

// ======================= K2: mma.sync fp16 GEMM + fused epilogue (round-6 proven) =======================
// CTA 128x128, BK=32, 16 K-stages, 5-stage cp.async ring, ONE sync per stage.
#define TILE_B   10240
#define STAGE_B  20480
#define NSTG     5
#define SMEM_DYN (NSTG * STAGE_B)          // 102400 ; epilogue reuses first 67584 B
#define LDT      40

__global__ __launch_bounds__(256, 2) void k_gemm_mma(const float* __restrict__ b2) {
    extern __shared__ char sm[];
    uint32_t smb = smem_u32(sm);
    int tid = threadIdx.x;
    int wid = tid >> 5, lane = tid & 31;
    int wm = wid >> 2, wn = wid & 3;            // warp grid 2(m) x 4(n), warp tile 64x32

    // L2-friendly swizzle: strips of (64 row-tiles x 8 col-tiles)
    int bid = blockIdx.x;
    int rt = (bid & 511) >> 3;
    int ct = ((bid >> 9) << 3) | (bid & 7);
    int row0 = rt * 128, col0 = ct * 128;

    float c[4][4][4];
#pragma unroll
    for (int i = 0; i < 4; i++)
#pragma unroll
        for (int j = 0; j < 4; j++)
#pragma unroll
            for (int q = 0; q < 4; q++) c[i][j][q] = 0.f;

    auto load_stage = [&](int s, int st) {
        uint32_t sb = smb + st * STAGE_B;
#pragma unroll
        for (int v = 0; v < 2; v++) {
            int f = tid + v * 256;              // 0..511
            int r = f >> 2, cq = f & 3;
            uint32_t soff = r * (LDT * 2) + cq * 16;
            size_t ga = ((size_t)(row0 + r) << 10) + (size_t)s * 64 + cq * 16;
            size_t gb = ((size_t)(col0 + r) << 10) + (size_t)s * 64 + cq * 16;
            CP16(sb + soff,          (const char*)g_Hh  + ga);
            CP16(sb + TILE_B + soff, (const char*)g_W2h + gb);
        }
    };

    load_stage(0, 0); CP_COMMIT();
    load_stage(1, 1); CP_COMMIT();
    load_stage(2, 2); CP_COMMIT();

    int bc = 0, bl = 3;
    for (int s = 0; s < 16; s++) {
        if (s + 3 < 16) {
            load_stage(s + 3, bl); CP_COMMIT();
            if (++bl == NSTG) bl = 0;
        }
        if (s < 13)      CP_WAIT(3);
        else if (s < 14) CP_WAIT(2);
        else if (s < 15) CP_WAIT(1);
        else             CP_WAIT(0);
        __syncthreads();

        uint32_t base = smb + bc * STAGE_B;
        if (++bc == NSTG) bc = 0;
#pragma unroll
        for (int ks = 0; ks < 2; ks++) {
            uint32_t a[4][4], bh[2][4];
            {
                int arow = wm * 64 + (lane & 15);
                int ak = ks * 16 + ((lane >> 4) << 3);
                uint32_t aoff = base + (uint32_t)(arow * (LDT * 2) + ak * 2);
#pragma unroll
                for (int i = 0; i < 4; i++) ldsm4(a[i], aoff + i * 16 * (LDT * 2));
            }
            {
                int g = lane >> 3, r = lane & 7;
                int bn = wn * 32 + ((g >> 1) << 3) + r;
                int bk = ks * 16 + ((g & 1) << 3);
                uint32_t boff = base + TILE_B + (uint32_t)(bn * (LDT * 2) + bk * 2);
#pragma unroll
                for (int j = 0; j < 2; j++)
                    ldsm4(bh[j], boff + j * 16 * (LDT * 2));
            }
#pragma unroll
            for (int i = 0; i < 4; i++)
#pragma unroll
                for (int jj = 0; jj < 4; jj++)
                    mma16816(c[i][jj], a[i], &bh[jj >> 1][(jj & 1) * 2]);
        }
    }
    __syncthreads();   // protect smem reuse by epilogue

    // ---- epilogue: stage in smem (stride 130), bias + relu + ex2, fp16 writes ----
    float* eb = (float*)sm;                      // 128 x 130 floats = 66560 B
    float* red = (float*)(sm + 66560);           // 2 x 128 floats
#pragma unroll
    for (int i = 0; i < 4; i++) {
#pragma unroll
        for (int jj = 0; jj < 4; jj++) {
            int r = wm * 64 + i * 16 + (lane >> 2);
            int cc = wn * 32 + jj * 8 + (lane & 3) * 2;
            *(float2*)&eb[r * 130 + cc]       = make_float2(c[i][jj][0], c[i][jj][1]);
            *(float2*)&eb[(r + 8) * 130 + cc] = make_float2(c[i][jj][2], c[i][jj][3]);
        }
    }
    __syncthreads();
    {
        int col = tid & 127, half = tid >> 7;
        float bias = b2[col0 + col] * LOG2E;
        float csum = 0.f;
        size_t gbase = (size_t)(row0 + half * 64) * Ee + col0 + col;
#pragma unroll 8
        for (int r = 0; r < 64; r++) {
            float v = ex2f(fmaxf(eb[(half * 64 + r) * 130 + col] + bias, 0.0f));
            csum += v;
            g_E[gbase + (size_t)r * Ee] = __float2half(v);
        }
        red[half * 128 + col] = csum;
    }
    __syncthreads();
    if (tid < 128)
        g_Zpart[(size_t)rt * Ee + col0 + tid] = red[tid] + red[128 + tid];
}

// ======================= K2b: softmax denominators =======================
__global__ void k_zreduce() {
    int idx = blockIdx.x * blockDim.x + threadIdx.x;
    int b = idx >> 13;
    int e = idx & (Ee - 1);
    float s = 0.f;
#pragma unroll
    for (int i = 0; i < 8; i++) s += g_Zpart[(size_t)(b * 8 + i) * Ee + e];
    g_Zinv[idx] = 1.0f / s;
}

// ======================= K3: normalize * xp, transpose, avgpool (4 rows/CTA) =======================
#define RPC 4
__global__ void k_final(const float* __restrict__ x, float* __restrict__ out) {
    int b = blockIdx.x >> 8;                 // 256 CTAs per batch
    int row0 = blockIdx.x * RPC;
    __shared__ float zs[Ee];                 // 32 KB: Zinv for this batch
    __shared__ float t[Pp * 514];            // 32.9 KB
    __shared__ float xs[Pp];
    int tid = threadIdx.x;                   // 512 threads

    {   // load Zinv[b,:] once
        const float4* Z4 = (const float4*)(g_Zinv + (size_t)b * Ee);
        float4* zs4 = (float4*)zs;
#pragma unroll
        for (int i = 0; i < 4; i++) zs4[i * 512 + tid] = Z4[i * 512 + tid];
    }

    for (int r = 0; r < RPC; r++) {
        int row = row0 + r;
        __syncthreads();
        if (tid < Pp) xs[tid] = x[row * Pp + tid] * (1.0f / 3.0f);
        const __half2* E2 = (const __half2*)(g_E + (size_t)row * Ee);
#pragma unroll
        for (int i = 0; i < 8; i++) {
            int idx2 = i * 512 + tid;        // half2 index: e = 2*idx2
            __half2 e2 = E2[idx2];
            int d = idx2 >> 3;
            int p0 = (idx2 & 7) * 2;
            int e = idx2 * 2;
            t[p0 * 514 + d]       = __low2float(e2)  * zs[e];
            t[(p0 + 1) * 514 + d] = __high2float(e2) * zs[e + 1];
        }
        __syncthreads();
        int d = tid;
        size_t obase = ((size_t)row * Pp) * Dd + d;
#pragma unroll
        for (int p = 0; p < Pp; p++) {
            const float* tp = t + p * 514;
            float cc = tp[d];
            float l = (d > 0)   ? tp[d - 1] : 0.f;
            float rr = (d < 511) ? tp[d + 1] : 0.f;
            out[obase + (size_t)p * Dd] = xs[p] * (l + cc + rr);
        }
    }
}

// ======================= launch =======================
extern "C" void kernel_launch(void* const* d_in, const int* in_sizes, int n_in,
                              void* d_out, int out_size) {
    const float* x  = (const float*)d_in[0];
    const float* W1 = (const float*)d_in[1];
    const float* b1 = (const float*)d_in[2];
    const float* W2 = (const float*)d_in[3];
    const float* b2 = (const float*)d_in[4];
    float* out = (float*)d_out;

    static int smem_set = 0;
    if (!smem_set) {
        cudaFuncSetAttribute(k_gemm_mma, cudaFuncAttributeMaxDynamicSharedMemorySize, SMEM_DYN);
        smem_set = 1;
    }

    k_prep<<<1536, 512>>>(x, W1, b1, W2);
    k_gemm_mma<<<4096, 256, SMEM_DYN>>>(b2);
    k_zreduce<<<(Bsz * Ee) / 256, 256>>>();
    k_final<<<Mm / RPC, 512>>>(x, out);
}